// round 7
// baseline (speedup 1.0000x reference)
#include <cuda_runtime.h>
#include <cstdint>

// ============================================================================
// GaussianMLP fused — sm_103 plain target, mma.sync m16n8k8 tf32.
// R7: R6 structure + software-pipelined fragment loads (ldsm issued >=4 mma
//     ahead of use; B frags double-buffered in registers).
// ============================================================================

#define NTILES 4096

__device__ __forceinline__ uint32_t smem_u32(const void* p) {
    uint32_t a;
    asm("{ .reg .u64 t; cvta.to.shared.u64 t, %1; cvt.u32.u64 %0, t; }" : "=r"(a) : "l"(p));
    return a;
}
__device__ __forceinline__ float rna_tf32(float x) {
    float r;
    asm("cvt.rna.tf32.f32 %0, %1;" : "=f"(r) : "f"(x));
    return r;
}
__device__ __forceinline__ void mma8(float* c, const uint32_t* a, uint32_t b0, uint32_t b1) {
    asm volatile(
        "mma.sync.aligned.m16n8k8.row.col.f32.tf32.tf32.f32 "
        "{%0,%1,%2,%3},{%4,%5,%6,%7},{%8,%9},{%0,%1,%2,%3};"
        : "+f"(c[0]), "+f"(c[1]), "+f"(c[2]), "+f"(c[3])
        : "r"(a[0]), "r"(a[1]), "r"(a[2]), "r"(a[3]), "r"(b0), "r"(b1));
}
__device__ __forceinline__ void ldsm4(uint32_t* r, uint32_t addr) {
    asm volatile("ldmatrix.sync.aligned.m8n8.x4.shared.b16 {%0,%1,%2,%3}, [%4];"
                 : "=r"(r[0]), "=r"(r[1]), "=r"(r[2]), "=r"(r[3]) : "r"(addr));
}
#define CP16CG(dst, src) \
    asm volatile("cp.async.cg.shared.global [%0], [%1], 16;" :: "r"(dst), "l"(src))
#define CP_COMMIT() asm volatile("cp.async.commit_group;" ::: "memory")
#define CP_WAIT1()  asm volatile("cp.async.wait_group 1;" ::: "memory")
#define CP_WAIT0()  asm volatile("cp.async.wait_group 0;" ::: "memory")

// ---------------- pre-rounded, pre-transposed weights ------------------------
__device__ __align__(16) float g_wemb_t[256 * 128];   // [n][k]
__device__ __align__(16) float g_w2_t[256 * 256];     // [n][k]  n<128: Wm, else Wl

__global__ void prep_kernel(const float* __restrict__ We,
                            const float* __restrict__ Wm,
                            const float* __restrict__ Wl) {
    int i = blockIdx.x * 256 + threadIdx.x;
    if (i < 32768) {
        int n = i >> 7, k = i & 127;
        g_wemb_t[i] = rna_tf32(We[k * 256 + n]);
    } else if (i < 98304) {
        int j = i - 32768;
        int n = j >> 8, k = j & 255;
        float v = (n < 128) ? Wm[k * 128 + n] : Wl[k * 128 + (n - 128)];
        g_w2_t[j] = rna_tf32(v);
    }
}

// ---------------- SMEM map (227328 B) ----------------------------------------
#define HS_OFF    0u
#define RING_OFF  133120u
#define SLOT_SZ   30720u
#define XOFF_IN_SLOT 20480u
#define SBE_OFF   225280u
#define SBM_OFF   226304u
#define SBL_OFF   226816u
#define SMEM_TOTAL 227328
#define HS_S 260
#define XW_S 20
#define MS_S 132

// 4 mma on one B fragment: p-block, both m halves.
#define MMAQ(p, Am0, Am1, B)                             \
    do {                                                 \
        mma8(acc[0][2*(p)],     Am0, (B)[0], (B)[1]);    \
        mma8(acc[0][2*(p) + 1], Am0, (B)[2], (B)[3]);    \
        mma8(acc[1][2*(p)],     Am1, (B)[0], (B)[1]);    \
        mma8(acc[1][2*(p) + 1], Am1, (B)[2], (B)[3]);    \
    } while (0)

__global__ void __launch_bounds__(512, 1)
gauss_kernel(const float* __restrict__ x, const float* __restrict__ eps,
             const float* __restrict__ be, const float* __restrict__ bm,
             const float* __restrict__ bl, float* __restrict__ out) {
    extern __shared__ char smem[];
    const uint32_t sm = smem_u32(smem);
    float* hs  = (float*)(smem + HS_OFF);
    float* sbe = (float*)(smem + SBE_OFF);
    float* sbm = (float*)(smem + SBM_OFF);
    float* sbl = (float*)(smem + SBL_OFF);

    const int tid  = threadIdx.x;
    const int wid  = tid >> 5, lane = tid & 31;
    const int g    = lane >> 2, tg = lane & 3;
    const int mw   = wid & 3;
    const int nw   = wid >> 2;
    const int nb   = nw * 64;
    const size_t tile = blockIdx.x;

    const int a_row  = (lane & 7) + ((lane & 8) ? 8 : 0);
    const int a_koff = (lane & 16) ? 4 : 0;
    const int b_n    = (lane & 7) + ((lane & 16) ? 8 : 0);
    const int b_koff = (lane & 8) ? 4 : 0;

    if (tid < 256) sbe[tid] = be[tid];
    if (tid < 128) { sbm[tid] = bm[tid]; sbl[tid] = bl[tid]; }

    const float* xg = x + tile * 16384;
    const int s_row = tid >> 2, s_q = tid & 3;

    auto slot_base = [&](int i) -> uint32_t {
        return sm + RING_OFF + (uint32_t)(i % 3) * SLOT_SZ;
    };
    auto issue_stage = [&](int i) {
        uint32_t base = slot_base(i);
        if (i < 8) {
            const float* w = g_wemb_t + i * 16;
            #pragma unroll
            for (int j = 0; j < 2; j++) {
                int row = s_row + j * 128;
                CP16CG(base + (uint32_t)(row * XW_S + s_q * 4) * 4u,
                       w + row * 128 + s_q * 4);
            }
            CP16CG(base + XOFF_IN_SLOT + (uint32_t)(s_row * XW_S + s_q * 4) * 4u,
                   xg + s_row * 128 + i * 16 + s_q * 4);
        } else {
            const float* w = g_w2_t + (i - 8) * 16;
            #pragma unroll
            for (int j = 0; j < 2; j++) {
                int row = s_row + j * 128;
                CP16CG(base + (uint32_t)(row * XW_S + s_q * 4) * 4u,
                       w + row * 256 + s_q * 4);
            }
        }
        CP_COMMIT();
    };

    float acc[2][8][4];
    #pragma unroll
    for (int m = 0; m < 2; m++)
        #pragma unroll
        for (int n = 0; n < 8; n++)
            #pragma unroll
            for (int c = 0; c < 4; c++) acc[m][n][c] = 0.0f;

    issue_stage(0);
    issue_stage(1);

    // ======================= layer 1 (stages 0..7) ===========================
    #pragma unroll 1
    for (int s = 0; s < 8; s++) {
        CP_WAIT1();
        __syncthreads();
        issue_stage(s + 2);

        const uint32_t base = slot_base(s);
        const uint32_t a0 = base + XOFF_IN_SLOT
            + (uint32_t)((mw * 32 + a_row) * XW_S + a_koff) * 4u;
        const uint32_t b0 = base + (uint32_t)((nb + b_n) * XW_S + b_koff) * 4u;
        #define AP1(m, kk) (a0 + (uint32_t)((m) * 16 * XW_S) * 4u + (kk) * 32u)
        #define BP1(p, kk) (b0 + (uint32_t)((p) * 16 * XW_S) * 4u + (kk) * 32u)

        uint32_t A0[4], A1[4], A2[4], A3[4], B0[4], B1[4];
        ldsm4(A0, AP1(0, 0)); ldsm4(A1, AP1(1, 0));
        ldsm4(B0, BP1(0, 0)); ldsm4(B1, BP1(1, 0));
        ldsm4(A2, AP1(0, 1)); ldsm4(A3, AP1(1, 1));
        #pragma unroll
        for (int c = 0; c < 4; c++) {
            A0[c] = __float_as_uint(rna_tf32(__uint_as_float(A0[c])));
            A1[c] = __float_as_uint(rna_tf32(__uint_as_float(A1[c])));
        }
        MMAQ(0, A0, A1, B0);
        ldsm4(B0, BP1(2, 0));
        #pragma unroll
        for (int c = 0; c < 4; c++) {
            A2[c] = __float_as_uint(rna_tf32(__uint_as_float(A2[c])));
            A3[c] = __float_as_uint(rna_tf32(__uint_as_float(A3[c])));
        }
        MMAQ(1, A0, A1, B1);
        ldsm4(B1, BP1(3, 0));
        MMAQ(2, A0, A1, B0);
        ldsm4(B0, BP1(0, 1));
        MMAQ(3, A0, A1, B1);
        ldsm4(B1, BP1(1, 1));
        MMAQ(0, A2, A3, B0);
        ldsm4(B0, BP1(2, 1));
        MMAQ(1, A2, A3, B1);
        ldsm4(B1, BP1(3, 1));
        MMAQ(2, A2, A3, B0);
        MMAQ(3, A2, A3, B1);
    }

    // ---- h = tf32(relu(acc + b_emb)) -> SMEM ----
    {
        #pragma unroll
        for (int m = 0; m < 2; m++) {
            const int r0 = mw * 32 + m * 16 + g;
            #pragma unroll
            for (int n = 0; n < 8; n++) {
                int col = nb + n * 8 + 2 * tg;
                float b0v = sbe[col], b1v = sbe[col + 1];
                float2 v0, v1;
                v0.x = rna_tf32(fmaxf(acc[m][n][0] + b0v, 0.0f));
                v0.y = rna_tf32(fmaxf(acc[m][n][1] + b1v, 0.0f));
                v1.x = rna_tf32(fmaxf(acc[m][n][2] + b0v, 0.0f));
                v1.y = rna_tf32(fmaxf(acc[m][n][3] + b1v, 0.0f));
                *(float2*)&hs[r0 * HS_S + col]       = v0;
                *(float2*)&hs[(r0 + 8) * HS_S + col] = v1;
            }
        }
    }
    #pragma unroll
    for (int m = 0; m < 2; m++)
        #pragma unroll
        for (int n = 0; n < 8; n++)
            #pragma unroll
            for (int c = 0; c < 4; c++) acc[m][n][c] = 0.0f;

    // ======================= layer 2 (stages 8..23) ==========================
    #pragma unroll 1
    for (int i = 8; i < 24; i++) {
        if (i == 23) { CP_WAIT0(); } else { CP_WAIT1(); }
        __syncthreads();
        if (i + 2 < 24) issue_stage(i + 2);

        const int c16 = i - 8;
        const uint32_t b0 = slot_base(i) + (uint32_t)((nb + b_n) * XW_S + b_koff) * 4u;
        const uint32_t a0 = sm + HS_OFF
            + (uint32_t)((mw * 32 + a_row) * HS_S + c16 * 16 + a_koff) * 4u;
        #define AP2(m, kk) (a0 + (uint32_t)((m) * 16 * HS_S) * 4u + (kk) * 32u)
        #define BP2(p, kk) (b0 + (uint32_t)((p) * 16 * XW_S) * 4u + (kk) * 32u)

        uint32_t A0[4], A1[4], A2[4], A3[4], B0[4], B1[4];
        ldsm4(A0, AP2(0, 0)); ldsm4(A1, AP2(1, 0));
        ldsm4(B0, BP2(0, 0)); ldsm4(B1, BP2(1, 0));
        ldsm4(A2, AP2(0, 1)); ldsm4(A3, AP2(1, 1));
        MMAQ(0, A0, A1, B0);
        ldsm4(B0, BP2(2, 0));
        MMAQ(1, A0, A1, B1);
        ldsm4(B1, BP2(3, 0));
        MMAQ(2, A0, A1, B0);
        ldsm4(B0, BP2(0, 1));
        MMAQ(3, A0, A1, B1);
        ldsm4(B1, BP2(1, 1));
        MMAQ(0, A2, A3, B0);
        ldsm4(B0, BP2(2, 1));
        MMAQ(1, A2, A3, B1);
        ldsm4(B1, BP2(3, 1));
        MMAQ(2, A2, A3, B0);
        MMAQ(3, A2, A3, B1);
    }
    __syncthreads();   // hs reads complete — reuse region for logvar exchange

    // ============== epilogue: register-direct, fragment layout ===============
    if (nw >= 2) {     // logvar warps (cols 128..255)
        float* ls = (float*)smem;
        const int cb2 = nb - 128;
        float* olg = out + 134217728u + tile * 16384;
        #pragma unroll
        for (int m = 0; m < 2; m++) {
            const int rA = mw * 32 + m * 16 + g, rB = rA + 8;
            #pragma unroll
            for (int n = 0; n < 8; n++) {
                int cc = cb2 + n * 8 + 2 * tg;
                float b0v = sbl[cc], b1v = sbl[cc + 1];
                float2 v0 = make_float2(acc[m][n][0] + b0v, acc[m][n][1] + b1v);
                float2 v1 = make_float2(acc[m][n][2] + b0v, acc[m][n][3] + b1v);
                *(float2*)&ls[rA * MS_S + cc] = v0;
                *(float2*)&ls[rB * MS_S + cc] = v1;
                *(float2*)&olg[rA * 128 + cc] = v0;
                *(float2*)&olg[rB * 128 + cc] = v1;
            }
        }
    }
    __syncthreads();
    if (nw < 2) {      // mean warps (cols 0..127)
        const float* ls = (const float*)smem;
        const float* eg = eps + tile * 16384;
        float* oz = out + tile * 16384;
        float* om = out + 67108864u + tile * 16384;
        #pragma unroll
        for (int m = 0; m < 2; m++) {
            const int rA = mw * 32 + m * 16 + g, rB = rA + 8;
            #pragma unroll
            for (int n = 0; n < 8; n++) {
                int cc = nb + n * 8 + 2 * tg;
                float b0v = sbm[cc], b1v = sbm[cc + 1];
                float2 m0 = make_float2(acc[m][n][0] + b0v, acc[m][n][1] + b1v);
                float2 m1 = make_float2(acc[m][n][2] + b0v, acc[m][n][3] + b1v);
                float2 l0 = *(const float2*)&ls[rA * MS_S + cc];
                float2 l1 = *(const float2*)&ls[rB * MS_S + cc];
                float2 e0 = *(const float2*)&eg[rA * 128 + cc];
                float2 e1 = *(const float2*)&eg[rB * 128 + cc];
                float2 z0, z1;
                z0.x = fmaf(__expf(0.5f * l0.x), e0.x, m0.x);
                z0.y = fmaf(__expf(0.5f * l0.y), e0.y, m0.y);
                z1.x = fmaf(__expf(0.5f * l1.x), e1.x, m1.x);
                z1.y = fmaf(__expf(0.5f * l1.y), e1.y, m1.y);
                *(float2*)&oz[rA * 128 + cc] = z0;
                *(float2*)&oz[rB * 128 + cc] = z1;
                *(float2*)&om[rA * 128 + cc] = m0;
                *(float2*)&om[rB * 128 + cc] = m1;
            }
        }
    }
}

// ---------------------------------------------------------------------------

extern "C" void kernel_launch(void* const* d_in, const int* in_sizes, int n_in,
                              void* d_out, int out_size) {
    const float* x   = (const float*)d_in[0];
    const float* eps = (const float*)d_in[1];
    const float* We  = (const float*)d_in[2];
    const float* be  = (const float*)d_in[3];
    const float* Wm  = (const float*)d_in[4];
    const float* bm  = (const float*)d_in[5];
    const float* Wl  = (const float*)d_in[6];
    const float* bl  = (const float*)d_in[7];
    float* out = (float*)d_out;

    cudaFuncSetAttribute(gauss_kernel, cudaFuncAttributeMaxDynamicSharedMemorySize, SMEM_TOTAL);
    prep_kernel<<<384, 256>>>(We, Wm, Wl);
    gauss_kernel<<<NTILES, 512, SMEM_TOTAL>>>(x, eps, be, bm, bl, out);
}

// round 8
// speedup vs baseline: 1.4827x; 1.4827x over previous
#include <cuda_runtime.h>
#include <cuda_fp16.h>
#include <cstdint>

// ============================================================================
// GaussianMLP fused — sm_103 plain target.
// R8: fp16 mma.sync.m16n8k16 (2x MACs/instr vs tf32 k8, same 11-bit mantissa).
//     512 thr, 4x4 warps, M32xN64 warp tile, 3-slot cp.async weight ring,
//     x converted fp32->half in-kernel (reg-prefetch double buffer).
// ============================================================================

#define NTILES 4096

__device__ __forceinline__ uint32_t smem_u32(const void* p) {
    uint32_t a;
    asm("{ .reg .u64 t; cvta.to.shared.u64 t, %1; cvt.u32.u64 %0, t; }" : "=r"(a) : "l"(p));
    return a;
}
__device__ __forceinline__ void mma16(float* c, const uint32_t* a, uint32_t b0, uint32_t b1) {
    asm volatile(
        "mma.sync.aligned.m16n8k16.row.col.f32.f16.f16.f32 "
        "{%0,%1,%2,%3},{%4,%5,%6,%7},{%8,%9},{%0,%1,%2,%3};"
        : "+f"(c[0]), "+f"(c[1]), "+f"(c[2]), "+f"(c[3])
        : "r"(a[0]), "r"(a[1]), "r"(a[2]), "r"(a[3]), "r"(b0), "r"(b1));
}
__device__ __forceinline__ void ldsm4(uint32_t* r, uint32_t addr) {
    asm volatile("ldmatrix.sync.aligned.m8n8.x4.shared.b16 {%0,%1,%2,%3}, [%4];"
                 : "=r"(r[0]), "=r"(r[1]), "=r"(r[2]), "=r"(r[3]) : "r"(addr));
}
#define CP16CG(dst, src) \
    asm volatile("cp.async.cg.shared.global [%0], [%1], 16;" :: "r"(dst), "l"(src))
#define CP_COMMIT() asm volatile("cp.async.commit_group;" ::: "memory")
#define CP_WAIT1()  asm volatile("cp.async.wait_group 1;" ::: "memory")
#define CP_WAIT0()  asm volatile("cp.async.wait_group 0;" ::: "memory")

// ---------------- pre-converted half weights, [n][k] -------------------------
__device__ __align__(16) __half g_wemb_h[256 * 128];  // n<256, k<128
__device__ __align__(16) __half g_w2_h[256 * 256];    // n<128: Wm, else Wl

__global__ void prep_kernel(const float* __restrict__ We,
                            const float* __restrict__ Wm,
                            const float* __restrict__ Wl) {
    int i = blockIdx.x * 256 + threadIdx.x;
    if (i < 32768) {
        int n = i >> 7, k = i & 127;
        g_wemb_h[i] = __float2half(We[k * 256 + n]);
    } else if (i < 98304) {
        int j = i - 32768;
        int n = j >> 8, k = j & 255;
        float v = (n < 128) ? Wm[k * 128 + n] : Wl[k * 128 + (n - 128)];
        g_w2_h[j] = __float2half(v);
    }
}

// ---------------- SMEM map (151552 B) ----------------------------------------
// hs   : h half tile [128][264]            67584  (reused: float ls [128][132])
// xs   : 2 x [128][40] half x chunks       20480
// ring : 3 x [256][40] half W chunks       61440
// bias : 2048
#define HS_OFF    0u
#define XS0_OFF   67584u
#define XS1_OFF   77824u
#define RING_OFF  88064u
#define SLOT_SZ   20480u
#define SBE_OFF   149504u
#define SBM_OFF   150528u
#define SBL_OFF   151040u
#define SMEM_TOTAL 151552
#define HS_S 264          // halves
#define XW_S 40           // halves (32 + 8 pad) -> 80 B rows, conflict-free
#define MS_S 132          // floats (epilogue logvar exchange)

__global__ void __launch_bounds__(512, 1)
gauss_kernel(const float* __restrict__ x, const float* __restrict__ eps,
             const float* __restrict__ be, const float* __restrict__ bm,
             const float* __restrict__ bl, float* __restrict__ out) {
    extern __shared__ char smem[];
    const uint32_t sm = smem_u32(smem);
    float* sbe = (float*)(smem + SBE_OFF);
    float* sbm = (float*)(smem + SBM_OFF);
    float* sbl = (float*)(smem + SBL_OFF);

    const int tid  = threadIdx.x;
    const int wid  = tid >> 5, lane = tid & 31;
    const int g    = lane >> 2, tg = lane & 3;
    const int mw   = wid & 3;                 // M block (32 rows)
    const int nw   = wid >> 2;                // N block (64 cols)
    const int nb   = nw * 64;
    const size_t tile = blockIdx.x;

    // ldmatrix lane address components (b16 fragments)
    const int fr_row = lane & 15;                    // row within 16-row block
    const int fr_ko  = (lane & 16) ? 8 : 0;          // k offset (halves)

    if (tid < 256) sbe[tid] = be[tid];
    if (tid < 128) { sbm[tid] = bm[tid]; sbl[tid] = bl[tid]; }

    const float* xg = x + tile * 16384;
    // x staging: 128 rows x 4 threads/row, each 8 floats
    const int x_row = tid >> 2, x_q = tid & 3;

    const uint32_t xsb[2] = { sm + XS0_OFF, sm + XS1_OFF };

    auto issue_stage = [&](int i) {                  // W chunk, K=32 halves
        if (i >= 12) return;
        uint32_t base = sm + RING_OFF + (uint32_t)(i % 3) * SLOT_SZ;
        const __half* w = (i < 4) ? (g_wemb_h + i * 32) : (g_w2_h + (i - 4) * 32);
        const int rs = (i < 4) ? 128 : 256;
        const int row = tid >> 1, seg = (tid & 1) * 2;
        CP16CG(base + (uint32_t)(row * 80 + seg * 16),       w + row * rs + seg * 8);
        CP16CG(base + (uint32_t)(row * 80 + (seg + 1) * 16), w + row * rs + (seg + 1) * 8);
        CP_COMMIT();
    };
    auto ldg_x = [&](int s, float4& v0, float4& v1) {
        const float* p = xg + x_row * 128 + s * 32 + x_q * 8;
        v0 = *(const float4*)p;
        v1 = *(const float4*)(p + 4);
    };
    auto sts_x = [&](int s, const float4& v0, const float4& v1) {
        __half2 h0 = __floats2half2_rn(v0.x, v0.y);
        __half2 h1 = __floats2half2_rn(v0.z, v0.w);
        __half2 h2 = __floats2half2_rn(v1.x, v1.y);
        __half2 h3 = __floats2half2_rn(v1.z, v1.w);
        uint4 u;
        u.x = *(uint32_t*)&h0; u.y = *(uint32_t*)&h1;
        u.z = *(uint32_t*)&h2; u.w = *(uint32_t*)&h3;
        *(uint4*)(smem + (XS0_OFF + (uint32_t)(s & 1) * 10240u)
                  + (uint32_t)(x_row * 80 + x_q * 16)) = u;
    };

    float acc[2][8][4];
    #pragma unroll
    for (int m = 0; m < 2; m++)
        #pragma unroll
        for (int n = 0; n < 8; n++)
            #pragma unroll
            for (int c = 0; c < 4; c++) acc[m][n][c] = 0.0f;

    // prologue
    issue_stage(0);
    issue_stage(1);
    float4 xr0, xr1;
    ldg_x(0, xr0, xr1);
    sts_x(0, xr0, xr1);
    ldg_x(1, xr0, xr1);

    // ======================= layer 1 (stages 0..3, K=32 each) ================
    #pragma unroll 1
    for (int s = 0; s < 4; s++) {
        CP_WAIT1();
        __syncthreads();                 // W[s] + x[s] visible; slot s-1 free
        issue_stage(s + 2);
        if (s < 3) {
            sts_x(s + 1, xr0, xr1);      // visible at next barrier
            if (s < 2) ldg_x(s + 2, xr0, xr1);
        }

        const uint32_t a_base = xsb[s & 1]
            + (uint32_t)((mw * 32 + fr_row) * XW_S + fr_ko) * 2u;
        const uint32_t b_base = sm + RING_OFF + (uint32_t)(s % 3) * SLOT_SZ
            + (uint32_t)((nb + fr_row) * XW_S + fr_ko) * 2u;
        #pragma unroll
        for (int kk = 0; kk < 2; kk++) {
            uint32_t A0[4], A1[4];
            ldsm4(A0, a_base + kk * 32u);
            ldsm4(A1, a_base + 1280u + kk * 32u);        // +16 rows
            #pragma unroll
            for (int q = 0; q < 4; q++) {
                uint32_t B[4];
                ldsm4(B, b_base + (uint32_t)(q * 16 * 80) + kk * 32u);
                mma16(acc[0][2 * q],     A0, B[0], B[2]);
                mma16(acc[0][2 * q + 1], A0, B[1], B[3]);
                mma16(acc[1][2 * q],     A1, B[0], B[2]);
                mma16(acc[1][2 * q + 1], A1, B[1], B[3]);
            }
        }
    }

    // ---- h = half(relu(acc + b_emb)) -> SMEM ----
    {
        #pragma unroll
        for (int m = 0; m < 2; m++) {
            const int r0 = mw * 32 + m * 16 + g;
            #pragma unroll
            for (int n = 0; n < 8; n++) {
                int col = nb + n * 8 + 2 * tg;
                float b0v = sbe[col], b1v = sbe[col + 1];
                __half2 v0 = __floats2half2_rn(fmaxf(acc[m][n][0] + b0v, 0.0f),
                                               fmaxf(acc[m][n][1] + b1v, 0.0f));
                __half2 v1 = __floats2half2_rn(fmaxf(acc[m][n][2] + b0v, 0.0f),
                                               fmaxf(acc[m][n][3] + b1v, 0.0f));
                *(__half2*)(smem + HS_OFF + (uint32_t)(r0 * HS_S + col) * 2u)       = v0;
                *(__half2*)(smem + HS_OFF + (uint32_t)((r0 + 8) * HS_S + col) * 2u) = v1;
            }
        }
    }
    #pragma unroll
    for (int m = 0; m < 2; m++)
        #pragma unroll
        for (int n = 0; n < 8; n++)
            #pragma unroll
            for (int c = 0; c < 4; c++) acc[m][n][c] = 0.0f;

    // ======================= layer 2 (stages 4..11) ==========================
    #pragma unroll 1
    for (int i = 4; i < 12; i++) {
        if (i == 11) { CP_WAIT0(); } else { CP_WAIT1(); }
        __syncthreads();                 // W[i] + (i==4: h tile) visible
        issue_stage(i + 2);

        const int c32 = i - 4;
        const uint32_t a_base = sm + HS_OFF
            + (uint32_t)((mw * 32 + fr_row) * HS_S + c32 * 32 + fr_ko) * 2u;
        const uint32_t b_base = sm + RING_OFF + (uint32_t)(i % 3) * SLOT_SZ
            + (uint32_t)((nb + fr_row) * XW_S + fr_ko) * 2u;
        #pragma unroll
        for (int kk = 0; kk < 2; kk++) {
            uint32_t A0[4], A1[4];
            ldsm4(A0, a_base + kk * 32u);
            ldsm4(A1, a_base + 8448u + kk * 32u);        // +16 rows (HS_S)
            #pragma unroll
            for (int q = 0; q < 4; q++) {
                uint32_t B[4];
                ldsm4(B, b_base + (uint32_t)(q * 16 * 80) + kk * 32u);
                mma16(acc[0][2 * q],     A0, B[0], B[2]);
                mma16(acc[0][2 * q + 1], A0, B[1], B[3]);
                mma16(acc[1][2 * q],     A1, B[0], B[2]);
                mma16(acc[1][2 * q + 1], A1, B[1], B[3]);
            }
        }
    }
    __syncthreads();   // hs reads complete — reuse base region for logvar tile

    // ============== epilogue: register-direct, fragment layout ===============
    if (nw >= 2) {     // logvar warps (cols 128..255)
        float* ls = (float*)smem;
        const int cb2 = nb - 128;
        float* olg = out + 134217728u + tile * 16384;
        #pragma unroll
        for (int m = 0; m < 2; m++) {
            const int rA = mw * 32 + m * 16 + g, rB = rA + 8;
            #pragma unroll
            for (int n = 0; n < 8; n++) {
                int cc = cb2 + n * 8 + 2 * tg;
                float b0v = sbl[cc], b1v = sbl[cc + 1];
                float2 v0 = make_float2(acc[m][n][0] + b0v, acc[m][n][1] + b1v);
                float2 v1 = make_float2(acc[m][n][2] + b0v, acc[m][n][3] + b1v);
                *(float2*)&ls[rA * MS_S + cc] = v0;
                *(float2*)&ls[rB * MS_S + cc] = v1;
                *(float2*)&olg[rA * 128 + cc] = v0;
                *(float2*)&olg[rB * 128 + cc] = v1;
            }
        }
    }
    __syncthreads();
    if (nw < 2) {      // mean warps (cols 0..127)
        const float* ls = (const float*)smem;
        const float* eg = eps + tile * 16384;
        float* oz = out + tile * 16384;
        float* om = out + 67108864u + tile * 16384;
        #pragma unroll
        for (int m = 0; m < 2; m++) {
            const int rA = mw * 32 + m * 16 + g, rB = rA + 8;
            #pragma unroll
            for (int n = 0; n < 8; n++) {
                int cc = nb + n * 8 + 2 * tg;
                float b0v = sbm[cc], b1v = sbm[cc + 1];
                float2 m0 = make_float2(acc[m][n][0] + b0v, acc[m][n][1] + b1v);
                float2 m1 = make_float2(acc[m][n][2] + b0v, acc[m][n][3] + b1v);
                float2 l0 = *(const float2*)&ls[rA * MS_S + cc];
                float2 l1 = *(const float2*)&ls[rB * MS_S + cc];
                float2 e0 = *(const float2*)&eg[rA * 128 + cc];
                float2 e1 = *(const float2*)&eg[rB * 128 + cc];
                float2 z0, z1;
                z0.x = fmaf(__expf(0.5f * l0.x), e0.x, m0.x);
                z0.y = fmaf(__expf(0.5f * l0.y), e0.y, m0.y);
                z1.x = fmaf(__expf(0.5f * l1.x), e1.x, m1.x);
                z1.y = fmaf(__expf(0.5f * l1.y), e1.y, m1.y);
                *(float2*)&oz[rA * 128 + cc] = z0;
                *(float2*)&oz[rB * 128 + cc] = z1;
                *(float2*)&om[rA * 128 + cc] = m0;
                *(float2*)&om[rB * 128 + cc] = m1;
            }
        }
    }
}

// ---------------------------------------------------------------------------

extern "C" void kernel_launch(void* const* d_in, const int* in_sizes, int n_in,
                              void* d_out, int out_size) {
    const float* x   = (const float*)d_in[0];
    const float* eps = (const float*)d_in[1];
    const float* We  = (const float*)d_in[2];
    const float* be  = (const float*)d_in[3];
    const float* Wm  = (const float*)d_in[4];
    const float* bm  = (const float*)d_in[5];
    const float* Wl  = (const float*)d_in[6];
    const float* bl  = (const float*)d_in[7];
    float* out = (float*)d_out;

    cudaFuncSetAttribute(gauss_kernel, cudaFuncAttributeMaxDynamicSharedMemorySize, SMEM_TOTAL);
    prep_kernel<<<384, 256>>>(We, Wm, Wl);
    gauss_kernel<<<NTILES, 512, SMEM_TOTAL>>>(x, eps, be, bm, bl, out);
}